// round 12
// baseline (speedup 1.0000x reference)
#include <cuda_runtime.h>
#include <cuda_fp16.h>
#include <cstdint>
#include <math.h>

#define MB 8192
#define NB 4096
#define KB 2048
#define HDIM 1024

#define BM 128
#define BN 128                       // 4 gates x 32 h-columns
#define BK 64                        // fp16 elements per slab (128B rows)
#define STAGES 3
#define NSLABS (KB / BK)             // 32

#define A_TILE_BYTES (BM * BK * 2)   // 16384
#define B_TILE_BYTES (BN * BK * 2)   // 16384
#define STAGE_BYTES (A_TILE_BYTES + B_TILE_BYTES)      // 32768
#define SMEM_TOTAL (STAGES * STAGE_BYTES)              // 98304 (2 CTAs/SM)
#define EPI_PITCH 132                                  // floats per row

// Scratch: fp16 packed operands
__device__ __half g_A[(size_t)MB * KB];      // 32 MB  [x | h_prev]
__device__ __half g_W[(size_t)NB * KB];      // 16 MB  gate-interleaved [Wx|Wh]

__device__ __forceinline__ uint32_t smem_u32(const void* p) {
    uint32_t a;
    asm("{ .reg .u64 t; cvta.to.shared.u64 t, %1; cvt.u32.u64 %0, t; }"
        : "=r"(a) : "l"(p));
    return a;
}

#define CP_ASYNC16(dst, src) \
    asm volatile("cp.async.cg.shared.global [%0], [%1], 16;" \
                 :: "r"(dst), "l"(src) : "memory")
#define CP_COMMIT() asm volatile("cp.async.commit_group;" ::: "memory")
#define CP_WAIT(n)  asm volatile("cp.async.wait_group %0;" :: "n"(n) : "memory")

#define LDM_X4(r0, r1, r2, r3, addr) \
    asm volatile("ldmatrix.sync.aligned.m8n8.x4.shared.b16 {%0,%1,%2,%3}, [%4];" \
                 : "=r"(r0), "=r"(r1), "=r"(r2), "=r"(r3) : "r"(addr))

#define MMA_F16(d, a, b0, b1) \
    asm volatile("mma.sync.aligned.m16n8k16.row.col.f32.f16.f16.f32 " \
                 "{%0,%1,%2,%3}, {%4,%5,%6,%7}, {%8,%9}, {%0,%1,%2,%3};" \
                 : "+f"((d)[0]), "+f"((d)[1]), "+f"((d)[2]), "+f"((d)[3]) \
                 : "r"((a)[0]), "r"((a)[1]), "r"((a)[2]), "r"((a)[3]), \
                   "r"(b0), "r"(b1))

// XOR swizzle on (row, 16B-col) within a [rows x 128B] tile
__device__ __forceinline__ uint32_t swz(int row, int c16) {
    return (uint32_t)(row * 128 + ((c16 ^ (row & 7)) << 4));
}

__device__ __forceinline__ float sigmoidf_(float v) {
    return 1.0f / (1.0f + expf(-v));
}

// ---------------------------------------------------------------------------
// Pre-pass: round to fp16 once (rne).
//   g_A row m        = [x[m] | h_prev[m]]
//   g_W packed row p : p = (h>>5)*128 + gate*32 + (h&31)  <- W[gate*1024+h]
// ---------------------------------------------------------------------------
#define A4TOT ((size_t)MB * KB / 4)   // 4194304
#define W4TOT ((size_t)NB * KB / 4)   // 2097152

__global__ __launch_bounds__(256)
void pack_f16(const float* __restrict__ x, const float* __restrict__ h,
              const float* __restrict__ Wx, const float* __restrict__ Wh)
{
    size_t idx = (size_t)blockIdx.x * blockDim.x + threadIdx.x;
    if (idx >= A4TOT + W4TOT) return;

    const float* src;
    __half* dst;
    if (idx < A4TOT) {
        size_t row = idx >> 9;
        int col = (int)(idx & 511) << 2;
        src = (col < HDIM) ? (x + row * HDIM + col)
                           : (h + row * HDIM + col - HDIM);
        dst = g_A + (row << 11) + col;
    } else {
        size_t w = idx - A4TOT;
        size_t p = w >> 9;
        int col = (int)(w & 511) << 2;
        int hblk = (int)(p >> 7);          // 0..31
        int gate = (int)((p >> 5) & 3);
        int hoff = (int)(p & 31);
        size_t srow = (size_t)gate * 1024 + hblk * 32 + hoff;
        src = (col < HDIM) ? (Wx + srow * HDIM + col)
                           : (Wh + srow * HDIM + col - HDIM);
        dst = g_W + (p << 11) + col;
    }
    float4 v = *reinterpret_cast<const float4*>(src);
    __half2 h01 = __floats2half2_rn(v.x, v.y);
    __half2 h23 = __floats2half2_rn(v.z, v.w);
    uint2 o;
    o.x = *reinterpret_cast<uint32_t*>(&h01);
    o.y = *reinterpret_cast<uint32_t*>(&h23);
    *reinterpret_cast<uint2*>(dst) = o;
}

// ---------------------------------------------------------------------------
// Fused GEMM + LSTM cell.
// CTA 128x128xk64 fp16, 3-stage cp.async, 256 threads = 8 warps (2m x 4n),
// warp tile 64x32 (warp_n == gate), 2 CTAs/SM. Fully-rolled fragments:
// a[mi] reloads after its MMAs; b[0]/b[1] reload inside mi=3's split ni
// loop (liveness-exact WAR into the same registers, zero extra regs).
// ---------------------------------------------------------------------------
__global__ __launch_bounds__(256, 2)
void lstm_fused(const float* __restrict__ bias,
                const float* __restrict__ c_prev,
                float* __restrict__ out)
{
    extern __shared__ char smem[];
    const uint32_t tiles = smem_u32(smem);

    const int tid = threadIdx.x;
    const int wid = tid >> 5;
    const int lid = tid & 31;
    const int warp_m = wid & 1;        // 2 warps along M (64 rows)
    const int warp_n = wid >> 1;       // 4 warps along N (32 cols) == gate
    const int block_m = blockIdx.y * BM;
    const int block_n = blockIdx.x * BN;   // packed-W row base
    const int H0 = blockIdx.x * 32;        // h-column base

    float c[4][4][4];                  // 64 regs accumulator
#pragma unroll
    for (int i = 0; i < 4; i++)
#pragma unroll
        for (int j = 0; j < 4; j++)
#pragma unroll
            for (int q = 0; q < 4; q++)
                c[i][j][q] = 0.0f;

    const int ld_r   = tid >> 3;       // 0..31
    const int ld_c16 = tid & 7;

    auto load_stage = [&](int stg, int slab) {
        const int kk = slab * BK;
        const __half* Asrc = g_A + kk;
        const __half* Bsrc = g_W + kk;
        const uint32_t ab = tiles + stg * STAGE_BYTES;
        const uint32_t bb = ab + A_TILE_BYTES;
#pragma unroll
        for (int t = 0; t < 4; t++) {
            const int r = ld_r + t * 32;
            CP_ASYNC16(ab + swz(r, ld_c16),
                       Asrc + (size_t)(block_m + r) * KB + ld_c16 * 8);
            CP_ASYNC16(bb + swz(r, ld_c16),
                       Bsrc + (size_t)(block_n + r) * KB + ld_c16 * 8);
        }
    };

#pragma unroll
    for (int s = 0; s < STAGES - 1; s++) {
        load_stage(s, s);
        CP_COMMIT();
    }

    const int a_row_in = lid & 15;               // m within m16
    const int a_hi     = (lid >> 4) & 1;         // k8 half
    const int b_row_in = (lid & 7) + ((lid >> 4) & 1) * 8;   // n within n16
    const int b_hi     = (lid >> 3) & 1;         // k8 half

    // persistent fragment registers (single-buffered, liveness-rolled)
    uint32_t a[4][4];
    uint32_t b[2][4];

    const int arow0 = warp_m * 64 + a_row_in;
    const int brow0 = warp_n * 32 + b_row_in;

    int stg = 0;
    for (int slab = 0; slab < NSLABS; slab++) {
        CP_WAIT(STAGES - 2);
        __syncthreads();

        const int next = slab + (STAGES - 1);
        if (next < NSLABS) load_stage(stg == 0 ? STAGES - 1 : stg - 1, next);
        CP_COMMIT();

        const uint32_t Abase = tiles + stg * STAGE_BYTES;
        const uint32_t Bbase = Abase + A_TILE_BYTES;
        stg = (stg == STAGES - 1) ? 0 : stg + 1;

        // slab head: load ks=0 frags (B first so first MMA starts earliest)
#pragma unroll
        for (int j = 0; j < 2; j++)
            LDM_X4(b[j][0], b[j][1], b[j][2], b[j][3],
                   Bbase + swz(brow0 + j * 16, b_hi));
#pragma unroll
        for (int mi = 0; mi < 4; mi++)
            LDM_X4(a[mi][0], a[mi][1], a[mi][2], a[mi][3],
                   Abase + swz(arow0 + mi * 16, a_hi));

#pragma unroll
        for (int ks = 0; ks < 4; ks++) {
            const int kn = ks + 1;     // next k16 step
            // mi = 0..2: MMAs then roll a[mi] -> ks+1
#pragma unroll
            for (int mi = 0; mi < 3; mi++) {
#pragma unroll
                for (int ni = 0; ni < 4; ni++)
                    MMA_F16(c[mi][ni], a[mi],
                            b[ni >> 1][(ni & 1) * 2],
                            b[ni >> 1][(ni & 1) * 2 + 1]);
                if (ks < 3)
                    LDM_X4(a[mi][0], a[mi][1], a[mi][2], a[mi][3],
                           Abase + swz(arow0 + mi * 16, kn * 2 + a_hi));
            }
            // mi = 3: split ni loop; roll b[0], b[1], a[3] at exact death
            MMA_F16(c[3][0], a[3], b[0][0], b[0][1]);
            MMA_F16(c[3][1], a[3], b[0][2], b[0][3]);
            if (ks < 3)
                LDM_X4(b[0][0], b[0][1], b[0][2], b[0][3],
                       Bbase + swz(brow0, kn * 2 + b_hi));
            MMA_F16(c[3][2], a[3], b[1][0], b[1][1]);
            MMA_F16(c[3][3], a[3], b[1][2], b[1][3]);
            if (ks < 3) {
                LDM_X4(b[1][0], b[1][1], b[1][2], b[1][3],
                       Bbase + swz(brow0 + 16, kn * 2 + b_hi));
                LDM_X4(a[3][0], a[3][1], a[3][2], a[3][3],
                       Abase + swz(arow0 + 3 * 16, kn * 2 + a_hi));
            }
        }
    }

    // =================== fused epilogue ===================
    CP_WAIT(0);
    __syncthreads();   // mainloop smem reads done; reuse tile smem
    float* ep = reinterpret_cast<float*>(smem);   // 128 x EPI_PITCH floats

    // Phase 1: acc + bias -> smem, gate-interleaved:
    //   float idx = row*EPI_PITCH + 4*(hh ^ (row&7)) + gate    (hh in 0..31)
    const int g8 = lid >> 2;
    const int q  = lid & 3;
    const int gate = warp_n;
    const float* brow = bias + gate * 1024 + H0;
#pragma unroll
    for (int ni = 0; ni < 4; ni++) {
        const int hh = ni * 8 + q * 2;
        const float b0 = __ldg(brow + hh);
        const float b1 = __ldg(brow + hh + 1);
#pragma unroll
        for (int mi = 0; mi < 4; mi++) {
            const int row0 = warp_m * 64 + mi * 16 + g8;
#pragma unroll
            for (int half = 0; half < 2; half++) {
                const int row = row0 + half * 8;
                const int xr = row & 7;
                ep[row * EPI_PITCH + 4 * (hh ^ xr) + gate]
                    = c[mi][ni][half * 2 + 0] + b0;
                ep[row * EPI_PITCH + 4 * ((hh + 1) ^ xr) + gate]
                    = c[mi][ni][half * 2 + 1] + b1;
            }
        }
    }
    __syncthreads();

    // Phase 2: LSTM math. warp w -> rows [16w, 16w+16); lane -> h = lid
#pragma unroll
    for (int r = 0; r < 16; r++) {
        const int m = wid * 16 + r;
        const int xr = m & 7;
        const size_t gbase = (size_t)(block_m + m) * HDIM + H0;
        const int h = lid;
        float4 v = *reinterpret_cast<const float4*>(
            ep + m * EPI_PITCH + 4 * (h ^ xr));
        // v = (i, f, o, g)
        const float cp = __ldg(c_prev + gbase + h);
        const float ct = sigmoidf_(v.y) * cp + sigmoidf_(v.x) * tanhf(v.w);
        const float ht = sigmoidf_(v.z) * tanhf(ct);
        out[gbase + h] = ht;
        out[(size_t)MB * HDIM + gbase + h] = ct;
    }
}

extern "C" void kernel_launch(void* const* d_in, const int* in_sizes, int n_in,
                              void* d_out, int out_size)
{
    const float* x      = (const float*)d_in[0];
    const float* h_prev = (const float*)d_in[1];
    const float* c_prev = (const float*)d_in[2];
    const float* Wx     = (const float*)d_in[3];
    const float* Wh     = (const float*)d_in[4];
    const float* bias   = (const float*)d_in[5];
    float* out = (float*)d_out;

    size_t packtot = A4TOT + W4TOT;
    pack_f16<<<(int)((packtot + 255) / 256), 256>>>(x, h_prev, Wx, Wh);

    cudaFuncSetAttribute(lstm_fused,
                         cudaFuncAttributeMaxDynamicSharedMemorySize, SMEM_TOTAL);
    dim3 grid(NB / BN, MB / BM);   // (32, 64)
    lstm_fused<<<grid, 256, SMEM_TOTAL>>>(bias, c_prev, out);
}

// round 14
// speedup vs baseline: 1.0232x; 1.0232x over previous
#include <cuda_runtime.h>
#include <cuda_fp16.h>
#include <cstdint>
#include <math.h>

#define MB 8192
#define NB 4096
#define KB 2048
#define HDIM 1024

#define BM 128
#define BN 128                       // 4 gates x 32 h-columns
#define BK 64                        // fp16 elements per slab (128B rows)
#define STAGES 3
#define NSLABS (KB / BK)             // 32

#define A_TILE_BYTES (BM * BK * 2)   // 16384
#define B_TILE_BYTES (BN * BK * 2)   // 16384
#define STAGE_BYTES (A_TILE_BYTES + B_TILE_BYTES)      // 32768
#define SMEM_TOTAL (STAGES * STAGE_BYTES)              // 98304 (2 CTAs/SM)
#define EPI_PITCH 132                                  // floats per row

// Scratch: fp16 packed operands
__device__ __half g_A[(size_t)MB * KB];      // 32 MB  [x | h_prev]
__device__ __half g_W[(size_t)NB * KB];      // 16 MB  gate-interleaved [Wx|Wh]

__device__ __forceinline__ uint32_t smem_u32(const void* p) {
    uint32_t a;
    asm("{ .reg .u64 t; cvta.to.shared.u64 t, %1; cvt.u32.u64 %0, t; }"
        : "=r"(a) : "l"(p));
    return a;
}

#define CP_ASYNC16(dst, src) \
    asm volatile("cp.async.cg.shared.global [%0], [%1], 16;" \
                 :: "r"(dst), "l"(src) : "memory")
#define CP_COMMIT() asm volatile("cp.async.commit_group;" ::: "memory")
#define CP_WAIT(n)  asm volatile("cp.async.wait_group %0;" :: "n"(n) : "memory")

#define LDM_X4(r0, r1, r2, r3, addr) \
    asm volatile("ldmatrix.sync.aligned.m8n8.x4.shared.b16 {%0,%1,%2,%3}, [%4];" \
                 : "=r"(r0), "=r"(r1), "=r"(r2), "=r"(r3) : "r"(addr))

#define MMA_F16(d, a, b0, b1) \
    asm volatile("mma.sync.aligned.m16n8k16.row.col.f32.f16.f16.f32 " \
                 "{%0,%1,%2,%3}, {%4,%5,%6,%7}, {%8,%9}, {%0,%1,%2,%3};" \
                 : "+f"((d)[0]), "+f"((d)[1]), "+f"((d)[2]), "+f"((d)[3]) \
                 : "r"((a)[0]), "r"((a)[1]), "r"((a)[2]), "r"((a)[3]), \
                   "r"(b0), "r"(b1))

// XOR swizzle on (row, 16B-col) within a [rows x 128B] tile
__device__ __forceinline__ uint32_t swz(int row, int c16) {
    return (uint32_t)(row * 128 + ((c16 ^ (row & 7)) << 4));
}

__device__ __forceinline__ float sigmoidf_(float v) {
    return 1.0f / (1.0f + expf(-v));
}

// ---------------------------------------------------------------------------
// Pre-pass: round to fp16 once (rne), 8 floats per thread -> one 16B store.
//   g_A row m        = [x[m] | h_prev[m]]
//   g_W packed row p : p = (h>>5)*128 + gate*32 + (h&31)  <- W[gate*1024+h]
// ---------------------------------------------------------------------------
#define A8TOT ((size_t)MB * KB / 8)   // 2097152
#define W8TOT ((size_t)NB * KB / 8)   // 1048576

__global__ __launch_bounds__(256)
void pack_f16(const float* __restrict__ x, const float* __restrict__ h,
              const float* __restrict__ Wx, const float* __restrict__ Wh)
{
    size_t idx = (size_t)blockIdx.x * blockDim.x + threadIdx.x;
    if (idx >= A8TOT + W8TOT) return;

    const float* src;
    __half* dst;
    if (idx < A8TOT) {
        size_t row = idx >> 8;             // 256 8-float units per 2048 row
        int col = (int)(idx & 255) << 3;
        src = (col < HDIM) ? (x + row * HDIM + col)
                           : (h + row * HDIM + col - HDIM);
        dst = g_A + (row << 11) + col;
    } else {
        size_t w = idx - A8TOT;
        size_t p = w >> 8;
        int col = (int)(w & 255) << 3;
        int hblk = (int)(p >> 7);          // 0..31
        int gate = (int)((p >> 5) & 3);
        int hoff = (int)(p & 31);
        size_t srow = (size_t)gate * 1024 + hblk * 32 + hoff;
        src = (col < HDIM) ? (Wx + srow * HDIM + col)
                           : (Wh + srow * HDIM + col - HDIM);
        dst = g_W + (p << 11) + col;
    }
    float4 v0 = *reinterpret_cast<const float4*>(src);
    float4 v1 = *reinterpret_cast<const float4*>(src + 4);
    __half2 h01 = __floats2half2_rn(v0.x, v0.y);
    __half2 h23 = __floats2half2_rn(v0.z, v0.w);
    __half2 h45 = __floats2half2_rn(v1.x, v1.y);
    __half2 h67 = __floats2half2_rn(v1.z, v1.w);
    uint4 o;
    o.x = *reinterpret_cast<uint32_t*>(&h01);
    o.y = *reinterpret_cast<uint32_t*>(&h23);
    o.z = *reinterpret_cast<uint32_t*>(&h45);
    o.w = *reinterpret_cast<uint32_t*>(&h67);
    *reinterpret_cast<uint4*>(dst) = o;
}

// ---------------------------------------------------------------------------
// Fused GEMM + LSTM cell.  (mainloop = verified R12 ordering:
//  CP_WAIT -> __syncthreads -> issue next stage; wait-before-barrier is
//  REQUIRED because cp.async.wait_group is per-thread.)
// CTA 128x128xk64 fp16, 3-stage cp.async, 256 threads = 8 warps (2m x 4n),
// warp tile 64x32 (warp_n == gate), 2 CTAs/SM, liveness-rolled fragments.
// ---------------------------------------------------------------------------
__global__ __launch_bounds__(256, 2)
void lstm_fused(const float* __restrict__ bias,
                const float* __restrict__ c_prev,
                float* __restrict__ out)
{
    extern __shared__ char smem[];
    const uint32_t tiles = smem_u32(smem);

    const int tid = threadIdx.x;
    const int wid = tid >> 5;
    const int lid = tid & 31;
    const int warp_m = wid & 1;        // 2 warps along M (64 rows)
    const int warp_n = wid >> 1;       // 4 warps along N (32 cols) == gate
    const int block_m = blockIdx.y * BM;
    const int block_n = blockIdx.x * BN;   // packed-W row base
    const int H0 = blockIdx.x * 32;        // h-column base

    float c[4][4][4];                  // 64 regs accumulator
#pragma unroll
    for (int i = 0; i < 4; i++)
#pragma unroll
        for (int j = 0; j < 4; j++)
#pragma unroll
            for (int q = 0; q < 4; q++)
                c[i][j][q] = 0.0f;

    const int ld_r   = tid >> 3;       // 0..31
    const int ld_c16 = tid & 7;

    auto load_stage = [&](int stg, int slab) {
        const int kk = slab * BK;
        const __half* Asrc = g_A + kk;
        const __half* Bsrc = g_W + kk;
        const uint32_t ab = tiles + stg * STAGE_BYTES;
        const uint32_t bb = ab + A_TILE_BYTES;
#pragma unroll
        for (int t = 0; t < 4; t++) {
            const int r = ld_r + t * 32;
            CP_ASYNC16(ab + swz(r, ld_c16),
                       Asrc + (size_t)(block_m + r) * KB + ld_c16 * 8);
            CP_ASYNC16(bb + swz(r, ld_c16),
                       Bsrc + (size_t)(block_n + r) * KB + ld_c16 * 8);
        }
    };

#pragma unroll
    for (int s = 0; s < STAGES - 1; s++) {
        load_stage(s, s);
        CP_COMMIT();
    }

    const int a_row_in = lid & 15;               // m within m16
    const int a_hi     = (lid >> 4) & 1;         // k8 half
    const int b_row_in = (lid & 7) + ((lid >> 4) & 1) * 8;   // n within n16
    const int b_hi     = (lid >> 3) & 1;         // k8 half

    // persistent fragment registers (single-buffered, liveness-rolled)
    uint32_t a[4][4];
    uint32_t b[2][4];

    const int arow0 = warp_m * 64 + a_row_in;
    const int brow0 = warp_n * 32 + b_row_in;

    int stg = 0;
    for (int slab = 0; slab < NSLABS; slab++) {
        // per-thread wait FIRST, then barrier -> cross-thread visibility
        CP_WAIT(STAGES - 2);
        __syncthreads();

        const int next = slab + (STAGES - 1);
        if (next < NSLABS) load_stage(stg == 0 ? STAGES - 1 : stg - 1, next);
        CP_COMMIT();

        const uint32_t Abase = tiles + stg * STAGE_BYTES;
        const uint32_t Bbase = Abase + A_TILE_BYTES;
        stg = (stg == STAGES - 1) ? 0 : stg + 1;

        // slab head: load ks=0 frags (B first so first MMA starts earliest)
#pragma unroll
        for (int j = 0; j < 2; j++)
            LDM_X4(b[j][0], b[j][1], b[j][2], b[j][3],
                   Bbase + swz(brow0 + j * 16, b_hi));
#pragma unroll
        for (int mi = 0; mi < 4; mi++)
            LDM_X4(a[mi][0], a[mi][1], a[mi][2], a[mi][3],
                   Abase + swz(arow0 + mi * 16, a_hi));

#pragma unroll
        for (int ks = 0; ks < 4; ks++) {
            const int kn = ks + 1;     // next k16 step
            // mi = 0..2: MMAs then roll a[mi] -> ks+1
#pragma unroll
            for (int mi = 0; mi < 3; mi++) {
#pragma unroll
                for (int ni = 0; ni < 4; ni++)
                    MMA_F16(c[mi][ni], a[mi],
                            b[ni >> 1][(ni & 1) * 2],
                            b[ni >> 1][(ni & 1) * 2 + 1]);
                if (ks < 3)
                    LDM_X4(a[mi][0], a[mi][1], a[mi][2], a[mi][3],
                           Abase + swz(arow0 + mi * 16, kn * 2 + a_hi));
            }
            // mi = 3: split ni loop; roll b[0], b[1], a[3] at exact death
            MMA_F16(c[3][0], a[3], b[0][0], b[0][1]);
            MMA_F16(c[3][1], a[3], b[0][2], b[0][3]);
            if (ks < 3)
                LDM_X4(b[0][0], b[0][1], b[0][2], b[0][3],
                       Bbase + swz(brow0, kn * 2 + b_hi));
            MMA_F16(c[3][2], a[3], b[1][0], b[1][1]);
            MMA_F16(c[3][3], a[3], b[1][2], b[1][3]);
            if (ks < 3) {
                LDM_X4(b[1][0], b[1][1], b[1][2], b[1][3],
                       Bbase + swz(brow0 + 16, kn * 2 + b_hi));
                LDM_X4(a[3][0], a[3][1], a[3][2], a[3][3],
                       Abase + swz(arow0 + 3 * 16, kn * 2 + a_hi));
            }
        }
    }

    // =================== fused epilogue ===================
    CP_WAIT(0);
    __syncthreads();   // mainloop smem reads done; reuse tile smem
    float* ep = reinterpret_cast<float*>(smem);   // 128 x EPI_PITCH floats

    // Phase 1: acc + bias -> smem, gate-interleaved:
    //   float idx = row*EPI_PITCH + 4*(hh ^ (row&7)) + gate    (hh in 0..31)
    const int g8 = lid >> 2;
    const int q  = lid & 3;
    const int gate = warp_n;
    const float* brow = bias + gate * 1024 + H0;
#pragma unroll
    for (int ni = 0; ni < 4; ni++) {
        const int hh = ni * 8 + q * 2;
        const float b0 = __ldg(brow + hh);
        const float b1 = __ldg(brow + hh + 1);
#pragma unroll
        for (int mi = 0; mi < 4; mi++) {
            const int row0 = warp_m * 64 + mi * 16 + g8;
#pragma unroll
            for (int half = 0; half < 2; half++) {
                const int row = row0 + half * 8;
                const int xr = row & 7;
                ep[row * EPI_PITCH + 4 * (hh ^ xr) + gate]
                    = c[mi][ni][half * 2 + 0] + b0;
                ep[row * EPI_PITCH + 4 * ((hh + 1) ^ xr) + gate]
                    = c[mi][ni][half * 2 + 1] + b1;
            }
        }
    }
    __syncthreads();

    // Phase 2: LSTM math. warp w -> rows [16w, 16w+16); lane -> h = lid
#pragma unroll
    for (int r = 0; r < 16; r++) {
        const int m = wid * 16 + r;
        const int xr = m & 7;
        const size_t gbase = (size_t)(block_m + m) * HDIM + H0;
        const int h = lid;
        float4 v = *reinterpret_cast<const float4*>(
            ep + m * EPI_PITCH + 4 * (h ^ xr));
        // v = (i, f, o, g)
        const float cp = __ldg(c_prev + gbase + h);
        const float ct = sigmoidf_(v.y) * cp + sigmoidf_(v.x) * tanhf(v.w);
        const float ht = sigmoidf_(v.z) * tanhf(ct);
        out[gbase + h] = ht;
        out[(size_t)MB * HDIM + gbase + h] = ct;
    }
}

extern "C" void kernel_launch(void* const* d_in, const int* in_sizes, int n_in,
                              void* d_out, int out_size)
{
    const float* x      = (const float*)d_in[0];
    const float* h_prev = (const float*)d_in[1];
    const float* c_prev = (const float*)d_in[2];
    const float* Wx     = (const float*)d_in[3];
    const float* Wh     = (const float*)d_in[4];
    const float* bias   = (const float*)d_in[5];
    float* out = (float*)d_out;

    size_t packtot = A8TOT + W8TOT;   // 3145728 threads
    pack_f16<<<(int)((packtot + 255) / 256), 256>>>(x, h_prev, Wx, Wh);

    cudaFuncSetAttribute(lstm_fused,
                         cudaFuncAttributeMaxDynamicSharedMemorySize, SMEM_TOTAL);
    dim3 grid(NB / BN, MB / BM);   // (32, 64)
    lstm_fused<<<grid, 256, SMEM_TOTAL>>>(bias, c_prev, out);
}

// round 15
// speedup vs baseline: 1.0275x; 1.0042x over previous
#include <cuda_runtime.h>
#include <cuda_fp16.h>
#include <cstdint>
#include <math.h>

#define MB 8192
#define NB 4096
#define KB 2048
#define HDIM 1024

#define BM 128
#define BN 128                       // 4 gates x 32 h-columns
#define BK 64                        // fp16 elements per slab (128B rows)
#define STAGES 3
#define NSLABS (KB / BK)             // 32

#define A_TILE_BYTES (BM * BK * 2)   // 16384
#define B_TILE_BYTES (BN * BK * 2)   // 16384
#define STAGE_BYTES (A_TILE_BYTES + B_TILE_BYTES)      // 32768
#define SMEM_TOTAL (STAGES * STAGE_BYTES)              // 98304 (2 CTAs/SM)
#define EPI_PITCH 132                                  // floats per row

// Scratch: fp16 packed operands
__device__ __half g_A[(size_t)MB * KB];      // 32 MB  [x | h_prev]
__device__ __half g_W[(size_t)NB * KB];      // 16 MB  gate-interleaved [Wx|Wh]

__device__ __forceinline__ uint32_t smem_u32(const void* p) {
    uint32_t a;
    asm("{ .reg .u64 t; cvta.to.shared.u64 t, %1; cvt.u32.u64 %0, t; }"
        : "=r"(a) : "l"(p));
    return a;
}

#define CP_ASYNC16(dst, src) \
    asm volatile("cp.async.cg.shared.global [%0], [%1], 16;" \
                 :: "r"(dst), "l"(src) : "memory")
#define CP_COMMIT() asm volatile("cp.async.commit_group;" ::: "memory")
#define CP_WAIT(n)  asm volatile("cp.async.wait_group %0;" :: "n"(n) : "memory")

#define LDM_X4(r0, r1, r2, r3, addr) \
    asm volatile("ldmatrix.sync.aligned.m8n8.x4.shared.b16 {%0,%1,%2,%3}, [%4];" \
                 : "=r"(r0), "=r"(r1), "=r"(r2), "=r"(r3) : "r"(addr))

#define MMA_F16(d, a, b0, b1) \
    asm volatile("mma.sync.aligned.m16n8k16.row.col.f32.f16.f16.f32 " \
                 "{%0,%1,%2,%3}, {%4,%5,%6,%7}, {%8,%9}, {%0,%1,%2,%3};" \
                 : "+f"((d)[0]), "+f"((d)[1]), "+f"((d)[2]), "+f"((d)[3]) \
                 : "r"((a)[0]), "r"((a)[1]), "r"((a)[2]), "r"((a)[3]), \
                   "r"(b0), "r"(b1))

// XOR swizzle on (row, 16B-col) within a [rows x 128B] tile
__device__ __forceinline__ uint32_t swz(int row, int c16) {
    return (uint32_t)(row * 128 + ((c16 ^ (row & 7)) << 4));
}

__device__ __forceinline__ float sigmoidf_(float v) {
    return 1.0f / (1.0f + expf(-v));
}

// ---------------------------------------------------------------------------
// Pre-pass: round to fp16 once (rne), 8 floats per thread -> one 16B store.
//   g_A row m        = [x[m] | h_prev[m]]
//   g_W packed row p : p = (h>>5)*128 + gate*32 + (h&31)  <- W[gate*1024+h]
// ---------------------------------------------------------------------------
#define A8TOT ((size_t)MB * KB / 8)   // 2097152
#define W8TOT ((size_t)NB * KB / 8)   // 1048576

__global__ __launch_bounds__(256)
void pack_f16(const float* __restrict__ x, const float* __restrict__ h,
              const float* __restrict__ Wx, const float* __restrict__ Wh)
{
    size_t idx = (size_t)blockIdx.x * blockDim.x + threadIdx.x;
    if (idx >= A8TOT + W8TOT) return;

    const float* src;
    __half* dst;
    if (idx < A8TOT) {
        size_t row = idx >> 8;             // 256 8-float units per 2048 row
        int col = (int)(idx & 255) << 3;
        src = (col < HDIM) ? (x + row * HDIM + col)
                           : (h + row * HDIM + col - HDIM);
        dst = g_A + (row << 11) + col;
    } else {
        size_t w = idx - A8TOT;
        size_t p = w >> 8;
        int col = (int)(w & 255) << 3;
        int hblk = (int)(p >> 7);          // 0..31
        int gate = (int)((p >> 5) & 3);
        int hoff = (int)(p & 31);
        size_t srow = (size_t)gate * 1024 + hblk * 32 + hoff;
        src = (col < HDIM) ? (Wx + srow * HDIM + col)
                           : (Wh + srow * HDIM + col - HDIM);
        dst = g_W + (p << 11) + col;
    }
    float4 v0 = *reinterpret_cast<const float4*>(src);
    float4 v1 = *reinterpret_cast<const float4*>(src + 4);
    __half2 h01 = __floats2half2_rn(v0.x, v0.y);
    __half2 h23 = __floats2half2_rn(v0.z, v0.w);
    __half2 h45 = __floats2half2_rn(v1.x, v1.y);
    __half2 h67 = __floats2half2_rn(v1.z, v1.w);
    uint4 o;
    o.x = *reinterpret_cast<uint32_t*>(&h01);
    o.y = *reinterpret_cast<uint32_t*>(&h23);
    o.z = *reinterpret_cast<uint32_t*>(&h45);
    o.w = *reinterpret_cast<uint32_t*>(&h67);
    *reinterpret_cast<uint4*>(dst) = o;
}

// ---------------------------------------------------------------------------
// Fused GEMM + LSTM cell.  (mainloop = verified R12/R14 ordering:
//  CP_WAIT -> __syncthreads -> issue next stage; wait-before-barrier is
//  REQUIRED because cp.async.wait_group is per-thread.  The unconditional
//  CP_COMMIT also matters: empty tail groups push real groups to retirement
//  so CP_WAIT(1) at the last slabs covers the final real group.)
// CTA 128x128xk64 fp16, 3-stage cp.async, 256 threads = 8 warps (2m x 4n),
// warp tile 64x32 (warp_n == gate), 2 CTAs/SM, liveness-rolled fragments.
// NEW: #pragma unroll 3 on the slab loop — body stays ~4.8KB (fits L0 I$,
// vs ~50KB when fully unrolled) and the stage index is constant per copy.
// ---------------------------------------------------------------------------
__global__ __launch_bounds__(256, 2)
void lstm_fused(const float* __restrict__ bias,
                const float* __restrict__ c_prev,
                float* __restrict__ out)
{
    extern __shared__ char smem[];
    const uint32_t tiles = smem_u32(smem);

    const int tid = threadIdx.x;
    const int wid = tid >> 5;
    const int lid = tid & 31;
    const int warp_m = wid & 1;        // 2 warps along M (64 rows)
    const int warp_n = wid >> 1;       // 4 warps along N (32 cols) == gate
    const int block_m = blockIdx.y * BM;
    const int block_n = blockIdx.x * BN;   // packed-W row base
    const int H0 = blockIdx.x * 32;        // h-column base

    float c[4][4][4];                  // 64 regs accumulator
#pragma unroll
    for (int i = 0; i < 4; i++)
#pragma unroll
        for (int j = 0; j < 4; j++)
#pragma unroll
            for (int q = 0; q < 4; q++)
                c[i][j][q] = 0.0f;

    const int ld_r   = tid >> 3;       // 0..31
    const int ld_c16 = tid & 7;

    auto load_stage = [&](int stg, int slab) {
        const int kk = slab * BK;
        const __half* Asrc = g_A + kk;
        const __half* Bsrc = g_W + kk;
        const uint32_t ab = tiles + stg * STAGE_BYTES;
        const uint32_t bb = ab + A_TILE_BYTES;
#pragma unroll
        for (int t = 0; t < 4; t++) {
            const int r = ld_r + t * 32;
            CP_ASYNC16(ab + swz(r, ld_c16),
                       Asrc + (size_t)(block_m + r) * KB + ld_c16 * 8);
            CP_ASYNC16(bb + swz(r, ld_c16),
                       Bsrc + (size_t)(block_n + r) * KB + ld_c16 * 8);
        }
    };

#pragma unroll
    for (int s = 0; s < STAGES - 1; s++) {
        load_stage(s, s);
        CP_COMMIT();
    }

    const int a_row_in = lid & 15;               // m within m16
    const int a_hi     = (lid >> 4) & 1;         // k8 half
    const int b_row_in = (lid & 7) + ((lid >> 4) & 1) * 8;   // n within n16
    const int b_hi     = (lid >> 3) & 1;         // k8 half

    // persistent fragment registers (single-buffered, liveness-rolled)
    uint32_t a[4][4];
    uint32_t b[2][4];

    const int arow0 = warp_m * 64 + a_row_in;
    const int brow0 = warp_n * 32 + b_row_in;

#pragma unroll 3
    for (int slab = 0; slab < NSLABS; slab++) {
        // per-thread wait FIRST, then barrier -> cross-thread visibility
        CP_WAIT(STAGES - 2);
        __syncthreads();

        const int stg = slab % STAGES;   // constant within each unrolled copy
        const int next = slab + (STAGES - 1);
        if (next < NSLABS) load_stage(next % STAGES, next);
        CP_COMMIT();

        const uint32_t Abase = tiles + stg * STAGE_BYTES;
        const uint32_t Bbase = Abase + A_TILE_BYTES;

        // slab head: load ks=0 frags (B first so first MMA starts earliest)
#pragma unroll
        for (int j = 0; j < 2; j++)
            LDM_X4(b[j][0], b[j][1], b[j][2], b[j][3],
                   Bbase + swz(brow0 + j * 16, b_hi));
#pragma unroll
        for (int mi = 0; mi < 4; mi++)
            LDM_X4(a[mi][0], a[mi][1], a[mi][2], a[mi][3],
                   Abase + swz(arow0 + mi * 16, a_hi));

#pragma unroll
        for (int ks = 0; ks < 4; ks++) {
            const int kn = ks + 1;     // next k16 step
            // mi = 0..2: MMAs then roll a[mi] -> ks+1
#pragma unroll
            for (int mi = 0; mi < 3; mi++) {
#pragma unroll
                for (int ni = 0; ni < 4; ni++)
                    MMA_F16(c[mi][ni], a[mi],
                            b[ni >> 1][(ni & 1) * 2],
                            b[ni >> 1][(ni & 1) * 2 + 1]);
                if (ks < 3)
                    LDM_X4(a[mi][0], a[mi][1], a[mi][2], a[mi][3],
                           Abase + swz(arow0 + mi * 16, kn * 2 + a_hi));
            }
            // mi = 3: split ni loop; roll b[0], b[1], a[3] at exact death
            MMA_F16(c[3][0], a[3], b[0][0], b[0][1]);
            MMA_F16(c[3][1], a[3], b[0][2], b[0][3]);
            if (ks < 3)
                LDM_X4(b[0][0], b[0][1], b[0][2], b[0][3],
                       Bbase + swz(brow0, kn * 2 + b_hi));
            MMA_F16(c[3][2], a[3], b[1][0], b[1][1]);
            MMA_F16(c[3][3], a[3], b[1][2], b[1][3]);
            if (ks < 3) {
                LDM_X4(b[1][0], b[1][1], b[1][2], b[1][3],
                       Bbase + swz(brow0 + 16, kn * 2 + b_hi));
                LDM_X4(a[3][0], a[3][1], a[3][2], a[3][3],
                       Abase + swz(arow0 + 3 * 16, kn * 2 + a_hi));
            }
        }
    }

    // =================== fused epilogue ===================
    CP_WAIT(0);
    __syncthreads();   // mainloop smem reads done; reuse tile smem
    float* ep = reinterpret_cast<float*>(smem);   // 128 x EPI_PITCH floats

    // Phase 1: acc + bias -> smem, gate-interleaved:
    //   float idx = row*EPI_PITCH + 4*(hh ^ (row&7)) + gate    (hh in 0..31)
    const int g8 = lid >> 2;
    const int q  = lid & 3;
    const int gate = warp_n;
    const float* brow = bias + gate * 1024 + H0;
#pragma unroll
    for (int ni = 0; ni < 4; ni++) {
        const int hh = ni * 8 + q * 2;
        const float b0 = __ldg(brow + hh);
        const float b1 = __ldg(brow + hh + 1);
#pragma unroll
        for (int mi = 0; mi < 4; mi++) {
            const int row0 = warp_m * 64 + mi * 16 + g8;
#pragma unroll
            for (int half = 0; half < 2; half++) {
                const int row = row0 + half * 8;
                const int xr = row & 7;
                ep[row * EPI_PITCH + 4 * (hh ^ xr) + gate]
                    = c[mi][ni][half * 2 + 0] + b0;
                ep[row * EPI_PITCH + 4 * ((hh + 1) ^ xr) + gate]
                    = c[mi][ni][half * 2 + 1] + b1;
            }
        }
    }
    __syncthreads();

    // Phase 2: LSTM math. warp w -> rows [16w, 16w+16); lane -> h = lid
#pragma unroll
    for (int r = 0; r < 16; r++) {
        const int m = wid * 16 + r;
        const int xr = m & 7;
        const size_t gbase = (size_t)(block_m + m) * HDIM + H0;
        const int h = lid;
        float4 v = *reinterpret_cast<const float4*>(
            ep + m * EPI_PITCH + 4 * (h ^ xr));
        // v = (i, f, o, g)
        const float cp = __ldg(c_prev + gbase + h);
        const float ct = sigmoidf_(v.y) * cp + sigmoidf_(v.x) * tanhf(v.w);
        const float ht = sigmoidf_(v.z) * tanhf(ct);
        out[gbase + h] = ht;
        out[(size_t)MB * HDIM + gbase + h] = ct;
    }
}

extern "C" void kernel_launch(void* const* d_in, const int* in_sizes, int n_in,
                              void* d_out, int out_size)
{
    const float* x      = (const float*)d_in[0];
    const float* h_prev = (const float*)d_in[1];
    const float* c_prev = (const float*)d_in[2];
    const float* Wx     = (const float*)d_in[3];
    const float* Wh     = (const float*)d_in[4];
    const float* bias   = (const float*)d_in[5];
    float* out = (float*)d_out;

    size_t packtot = A8TOT + W8TOT;   // 3145728 threads
    pack_f16<<<(int)((packtot + 255) / 256), 256>>>(x, h_prev, Wx, Wh);

    cudaFuncSetAttribute(lstm_fused,
                         cudaFuncAttributeMaxDynamicSharedMemorySize, SMEM_TOTAL);
    dim3 grid(NB / BN, MB / BM);   // (32, 64)
    lstm_fused<<<grid, 256, SMEM_TOTAL>>>(bias, c_prev, out);
}

// round 16
// speedup vs baseline: 1.0339x; 1.0062x over previous
#include <cuda_runtime.h>
#include <cuda_fp16.h>
#include <cstdint>
#include <math.h>

#define MB 8192
#define NB 4096
#define KB 2048
#define HDIM 1024

#define BM 128
#define BN 128                       // 4 gates x 32 h-columns
#define BK 64                        // fp16 elements per slab (128B rows)
#define STAGES 3
#define NSLABS (KB / BK)             // 32

#define A_TILE_BYTES (BM * BK * 2)   // 16384
#define B_TILE_BYTES (BN * BK * 2)   // 16384
#define STAGE_BYTES (A_TILE_BYTES + B_TILE_BYTES)      // 32768
#define SMEM_TOTAL (STAGES * STAGE_BYTES)              // 98304 (2 CTAs/SM)
#define EPI_PITCH 132                                  // floats per row (67584 B)
#define CPREV_OFF 81920                                // 80KB; 16KB region to 96KB

// Scratch: fp16 packed operands
__device__ __half g_A[(size_t)MB * KB];      // 32 MB  [x | h_prev]
__device__ __half g_W[(size_t)NB * KB];      // 16 MB  gate-interleaved [Wx|Wh]

__device__ __forceinline__ uint32_t smem_u32(const void* p) {
    uint32_t a;
    asm("{ .reg .u64 t; cvta.to.shared.u64 t, %1; cvt.u32.u64 %0, t; }"
        : "=r"(a) : "l"(p));
    return a;
}

#define CP_ASYNC16(dst, src) \
    asm volatile("cp.async.cg.shared.global [%0], [%1], 16;" \
                 :: "r"(dst), "l"(src) : "memory")
#define CP_COMMIT() asm volatile("cp.async.commit_group;" ::: "memory")
#define CP_WAIT(n)  asm volatile("cp.async.wait_group %0;" :: "n"(n) : "memory")

#define LDM_X4(r0, r1, r2, r3, addr) \
    asm volatile("ldmatrix.sync.aligned.m8n8.x4.shared.b16 {%0,%1,%2,%3}, [%4];" \
                 : "=r"(r0), "=r"(r1), "=r"(r2), "=r"(r3) : "r"(addr))

#define MMA_F16(d, a, b0, b1) \
    asm volatile("mma.sync.aligned.m16n8k16.row.col.f32.f16.f16.f32 " \
                 "{%0,%1,%2,%3}, {%4,%5,%6,%7}, {%8,%9}, {%0,%1,%2,%3};" \
                 : "+f"((d)[0]), "+f"((d)[1]), "+f"((d)[2]), "+f"((d)[3]) \
                 : "r"((a)[0]), "r"((a)[1]), "r"((a)[2]), "r"((a)[3]), \
                   "r"(b0), "r"(b1))

// XOR swizzle on (row, 16B-col) within a [rows x 128B] tile
__device__ __forceinline__ uint32_t swz(int row, int c16) {
    return (uint32_t)(row * 128 + ((c16 ^ (row & 7)) << 4));
}

__device__ __forceinline__ float sigmoidf_(float v) {
    return 1.0f / (1.0f + expf(-v));
}

// ---------------------------------------------------------------------------
// Pre-pass: round to fp16 once (rne), 8 floats per thread -> one 16B store.
//   g_A row m        = [x[m] | h_prev[m]]
//   g_W packed row p : p = (h>>5)*128 + gate*32 + (h&31)  <- W[gate*1024+h]
// ---------------------------------------------------------------------------
#define A8TOT ((size_t)MB * KB / 8)   // 2097152
#define W8TOT ((size_t)NB * KB / 8)   // 1048576

__global__ __launch_bounds__(256)
void pack_f16(const float* __restrict__ x, const float* __restrict__ h,
              const float* __restrict__ Wx, const float* __restrict__ Wh)
{
    size_t idx = (size_t)blockIdx.x * blockDim.x + threadIdx.x;
    if (idx >= A8TOT + W8TOT) return;

    const float* src;
    __half* dst;
    if (idx < A8TOT) {
        size_t row = idx >> 8;             // 256 8-float units per 2048 row
        int col = (int)(idx & 255) << 3;
        src = (col < HDIM) ? (x + row * HDIM + col)
                           : (h + row * HDIM + col - HDIM);
        dst = g_A + (row << 11) + col;
    } else {
        size_t w = idx - A8TOT;
        size_t p = w >> 8;
        int col = (int)(w & 255) << 3;
        int hblk = (int)(p >> 7);          // 0..31
        int gate = (int)((p >> 5) & 3);
        int hoff = (int)(p & 31);
        size_t srow = (size_t)gate * 1024 + hblk * 32 + hoff;
        src = (col < HDIM) ? (Wx + srow * HDIM + col)
                           : (Wh + srow * HDIM + col - HDIM);
        dst = g_W + (p << 11) + col;
    }
    float4 v0 = *reinterpret_cast<const float4*>(src);
    float4 v1 = *reinterpret_cast<const float4*>(src + 4);
    __half2 h01 = __floats2half2_rn(v0.x, v0.y);
    __half2 h23 = __floats2half2_rn(v0.z, v0.w);
    __half2 h45 = __floats2half2_rn(v1.x, v1.y);
    __half2 h67 = __floats2half2_rn(v1.z, v1.w);
    uint4 o;
    o.x = *reinterpret_cast<uint32_t*>(&h01);
    o.y = *reinterpret_cast<uint32_t*>(&h23);
    o.z = *reinterpret_cast<uint32_t*>(&h45);
    o.w = *reinterpret_cast<uint32_t*>(&h67);
    *reinterpret_cast<uint4*>(dst) = o;
}

// ---------------------------------------------------------------------------
// Fused GEMM + LSTM cell.  (mainloop = verified R12/R14 ordering:
//  CP_WAIT -> __syncthreads -> issue next stage; wait-before-barrier is
//  REQUIRED because cp.async.wait_group is per-thread.  Unconditional
//  CP_COMMIT keeps tail group accounting correct.)
// CTA 128x128xk64 fp16, 3-stage cp.async, 256 threads = 8 warps (2m x 4n),
// warp tile 64x32 (warp_n == gate), 2 CTAs/SM, liveness-rolled fragments,
// #pragma unroll 3 slab loop (fits L0 I$).
// NEW: c_prev tile prefetched via cp.async into spare smem at epilogue
// start; phase-1 covers the latency; phase-2 reads conflict-free LDS.
// ---------------------------------------------------------------------------
__global__ __launch_bounds__(256, 2)
void lstm_fused(const float* __restrict__ bias,
                const float* __restrict__ c_prev,
                float* __restrict__ out)
{
    extern __shared__ char smem[];
    const uint32_t tiles = smem_u32(smem);

    const int tid = threadIdx.x;
    const int wid = tid >> 5;
    const int lid = tid & 31;
    const int warp_m = wid & 1;        // 2 warps along M (64 rows)
    const int warp_n = wid >> 1;       // 4 warps along N (32 cols) == gate
    const int block_m = blockIdx.y * BM;
    const int block_n = blockIdx.x * BN;   // packed-W row base
    const int H0 = blockIdx.x * 32;        // h-column base

    float c[4][4][4];                  // 64 regs accumulator
#pragma unroll
    for (int i = 0; i < 4; i++)
#pragma unroll
        for (int j = 0; j < 4; j++)
#pragma unroll
            for (int q = 0; q < 4; q++)
                c[i][j][q] = 0.0f;

    const int ld_r   = tid >> 3;       // 0..31
    const int ld_c16 = tid & 7;

    auto load_stage = [&](int stg, int slab) {
        const int kk = slab * BK;
        const __half* Asrc = g_A + kk;
        const __half* Bsrc = g_W + kk;
        const uint32_t ab = tiles + stg * STAGE_BYTES;
        const uint32_t bb = ab + A_TILE_BYTES;
#pragma unroll
        for (int t = 0; t < 4; t++) {
            const int r = ld_r + t * 32;
            CP_ASYNC16(ab + swz(r, ld_c16),
                       Asrc + (size_t)(block_m + r) * KB + ld_c16 * 8);
            CP_ASYNC16(bb + swz(r, ld_c16),
                       Bsrc + (size_t)(block_n + r) * KB + ld_c16 * 8);
        }
    };

#pragma unroll
    for (int s = 0; s < STAGES - 1; s++) {
        load_stage(s, s);
        CP_COMMIT();
    }

    const int a_row_in = lid & 15;               // m within m16
    const int a_hi     = (lid >> 4) & 1;         // k8 half
    const int b_row_in = (lid & 7) + ((lid >> 4) & 1) * 8;   // n within n16
    const int b_hi     = (lid >> 3) & 1;         // k8 half

    // persistent fragment registers (single-buffered, liveness-rolled)
    uint32_t a[4][4];
    uint32_t b[2][4];

    const int arow0 = warp_m * 64 + a_row_in;
    const int brow0 = warp_n * 32 + b_row_in;

#pragma unroll 3
    for (int slab = 0; slab < NSLABS; slab++) {
        // per-thread wait FIRST, then barrier -> cross-thread visibility
        CP_WAIT(STAGES - 2);
        __syncthreads();

        const int stg = slab % STAGES;   // constant within each unrolled copy
        const int next = slab + (STAGES - 1);
        if (next < NSLABS) load_stage(next % STAGES, next);
        CP_COMMIT();

        const uint32_t Abase = tiles + stg * STAGE_BYTES;
        const uint32_t Bbase = Abase + A_TILE_BYTES;

        // slab head: load ks=0 frags (B first so first MMA starts earliest)
#pragma unroll
        for (int j = 0; j < 2; j++)
            LDM_X4(b[j][0], b[j][1], b[j][2], b[j][3],
                   Bbase + swz(brow0 + j * 16, b_hi));
#pragma unroll
        for (int mi = 0; mi < 4; mi++)
            LDM_X4(a[mi][0], a[mi][1], a[mi][2], a[mi][3],
                   Abase + swz(arow0 + mi * 16, a_hi));

#pragma unroll
        for (int ks = 0; ks < 4; ks++) {
            const int kn = ks + 1;     // next k16 step
            // mi = 0..2: MMAs then roll a[mi] -> ks+1
#pragma unroll
            for (int mi = 0; mi < 3; mi++) {
#pragma unroll
                for (int ni = 0; ni < 4; ni++)
                    MMA_F16(c[mi][ni], a[mi],
                            b[ni >> 1][(ni & 1) * 2],
                            b[ni >> 1][(ni & 1) * 2 + 1]);
                if (ks < 3)
                    LDM_X4(a[mi][0], a[mi][1], a[mi][2], a[mi][3],
                           Abase + swz(arow0 + mi * 16, kn * 2 + a_hi));
            }
            // mi = 3: split ni loop; roll b[0], b[1], a[3] at exact death
            MMA_F16(c[3][0], a[3], b[0][0], b[0][1]);
            MMA_F16(c[3][1], a[3], b[0][2], b[0][3]);
            if (ks < 3)
                LDM_X4(b[0][0], b[0][1], b[0][2], b[0][3],
                       Bbase + swz(brow0, kn * 2 + b_hi));
            MMA_F16(c[3][2], a[3], b[1][0], b[1][1]);
            MMA_F16(c[3][3], a[3], b[1][2], b[1][3]);
            if (ks < 3) {
                LDM_X4(b[1][0], b[1][1], b[1][2], b[1][3],
                       Bbase + swz(brow0 + 16, kn * 2 + b_hi));
                LDM_X4(a[3][0], a[3][1], a[3][2], a[3][3],
                       Abase + swz(arow0 + 3 * 16, kn * 2 + a_hi));
            }
        }
    }

    // =================== fused epilogue ===================
    CP_WAIT(0);
    __syncthreads();   // all mainloop smem reads done; smem reusable
    float* ep  = reinterpret_cast<float*>(smem);              // 128 x 132 floats
    float* cps = reinterpret_cast<float*>(smem + CPREV_OFF);  // 128 x 32 floats

    // prefetch this CTA's c_prev tile (128 rows x 32 h = 16KB): 1024 16B
    // chunks, 4 per thread.  Phase 1 below covers the copy latency.
    {
#pragma unroll
        for (int t = 0; t < 4; t++) {
            const int chunk = tid + t * 256;       // 0..1023
            const int m  = chunk >> 3;
            const int c8 = chunk & 7;
            CP_ASYNC16(tiles + CPREV_OFF + chunk * 16,
                       c_prev + (size_t)(block_m + m) * HDIM + H0 + c8 * 4);
        }
        CP_COMMIT();
    }

    // Phase 1: acc + bias -> smem, gate-interleaved:
    //   float idx = row*EPI_PITCH + 4*(hh ^ (row&7)) + gate    (hh in 0..31)
    const int g8 = lid >> 2;
    const int q  = lid & 3;
    const int gate = warp_n;
    const float* brow = bias + gate * 1024 + H0;
#pragma unroll
    for (int ni = 0; ni < 4; ni++) {
        const int hh = ni * 8 + q * 2;
        const float b0 = __ldg(brow + hh);
        const float b1 = __ldg(brow + hh + 1);
#pragma unroll
        for (int mi = 0; mi < 4; mi++) {
            const int row0 = warp_m * 64 + mi * 16 + g8;
#pragma unroll
            for (int half = 0; half < 2; half++) {
                const int row = row0 + half * 8;
                const int xr = row & 7;
                ep[row * EPI_PITCH + 4 * (hh ^ xr) + gate]
                    = c[mi][ni][half * 2 + 0] + b0;
                ep[row * EPI_PITCH + 4 * ((hh + 1) ^ xr) + gate]
                    = c[mi][ni][half * 2 + 1] + b1;
            }
        }
    }
    CP_WAIT(0);        // own c_prev chunks landed
    __syncthreads();   // everyone's ep writes + c_prev chunks visible

    // Phase 2: LSTM math. warp w -> rows [16w, 16w+16); lane -> h = lid
#pragma unroll
    for (int r = 0; r < 16; r++) {
        const int m = wid * 16 + r;
        const int xr = m & 7;
        const size_t gbase = (size_t)(block_m + m) * HDIM + H0;
        const int h = lid;
        float4 v = *reinterpret_cast<const float4*>(
            ep + m * EPI_PITCH + 4 * (h ^ xr));
        // v = (i, f, o, g)
        const float cp = cps[m * 32 + h];          // conflict-free LDS
        const float ct = sigmoidf_(v.y) * cp + sigmoidf_(v.x) * tanhf(v.w);
        const float ht = sigmoidf_(v.z) * tanhf(ct);
        out[gbase + h] = ht;
        out[(size_t)MB * HDIM + gbase + h] = ct;
    }
}

extern "C" void kernel_launch(void* const* d_in, const int* in_sizes, int n_in,
                              void* d_out, int out_size)
{
    const float* x      = (const float*)d_in[0];
    const float* h_prev = (const float*)d_in[1];
    const float* c_prev = (const float*)d_in[2];
    const float* Wx     = (const float*)d_in[3];
    const float* Wh     = (const float*)d_in[4];
    const float* bias   = (const float*)d_in[5];
    float* out = (float*)d_out;

    size_t packtot = A8TOT + W8TOT;   // 3145728 threads
    pack_f16<<<(int)((packtot + 255) / 256), 256>>>(x, h_prev, Wx, Wh);

    cudaFuncSetAttribute(lstm_fused,
                         cudaFuncAttributeMaxDynamicSharedMemorySize, SMEM_TOTAL);
    dim3 grid(NB / BN, MB / BM);   // (32, 64)
    lstm_fused<<<grid, 256, SMEM_TOTAL>>>(bias, c_prev, out);
}